// round 1
// baseline (speedup 1.0000x reference)
#include <cuda_runtime.h>
#include <cstdint>
#include <cstddef>

// Problem constants (fixed by the reference).
#define NG   128            // graphs
#define GSZ  128            // nodes per graph
#define DIM  512            // feature dim
#define NTOT (NG * GSZ)     // 16384 total nodes
#define NPAIR (GSZ * (GSZ - 1) / 2)   // 8128 upper-tri pairs per graph

// GEMM tile config
#define BM 128
#define BN 128
#define BK 16
#define TM 8
#define TN 8
#define NTHREADS 256

// ---------------------------------------------------------------------------
// Global min/max accumulators as order-preserving unsigned keys.
// key(f) is monotone increasing in f, so atomicMin/atomicMax on keys work.
// ---------------------------------------------------------------------------
__device__ unsigned g_min_key;
__device__ unsigned g_max_key;

__device__ __forceinline__ unsigned f2key(float f) {
    unsigned b = __float_as_uint(f);
    return (b & 0x80000000u) ? ~b : (b | 0x80000000u);
}
__device__ __forceinline__ float key2f(unsigned k) {
    unsigned b = (k & 0x80000000u) ? (k ^ 0x80000000u) : ~k;
    return __uint_as_float(b);
}

__global__ void lp_init_kernel() {
    g_min_key = 0xFFFFFFFFu;   // encodes +inf side (largest key)
    g_max_key = 0u;            // encodes -inf side (smallest key)
}

// ---------------------------------------------------------------------------
// Shared Gram-tile accumulator: computes a 128x128 block of A_rows · B_rowsᵀ
// over K=DIM into per-thread 8x8 registers. A and B are row pointers into E
// (row-major, stride DIM). 256 threads.
// ---------------------------------------------------------------------------
__device__ __forceinline__ void gram_tile_128x128(
    const float* __restrict__ Aptr,
    const float* __restrict__ Bptr,
    float acc[TM][TN])
{
    __shared__ float As[BK][BM + 4];   // transposed: As[k][m], +4 pad vs bank conflicts
    __shared__ float Bs[BK][BN + 4];

    const int tid  = threadIdx.x;
    const int lrow = tid >> 2;          // 0..63 (row within 64-row load pass)
    const int lk   = (tid & 3) << 2;    // k offset within BK: 0,4,8,12
    const int tr   = (tid >> 4) << 3;   // 0..120, row base of 8x8 micro tile
    const int tc   = (tid & 15) << 3;   // 0..120, col base

    for (int k0 = 0; k0 < DIM; k0 += BK) {
        // Load 128x16 A tile and 128x16 B tile, transposed into smem.
        #pragma unroll
        for (int r = 0; r < BM; r += 64) {
            float4 va = *(const float4*)(Aptr + (size_t)(lrow + r) * DIM + (k0 + lk));
            float4 vb = *(const float4*)(Bptr + (size_t)(lrow + r) * DIM + (k0 + lk));
            As[lk + 0][lrow + r] = va.x;
            As[lk + 1][lrow + r] = va.y;
            As[lk + 2][lrow + r] = va.z;
            As[lk + 3][lrow + r] = va.w;
            Bs[lk + 0][lrow + r] = vb.x;
            Bs[lk + 1][lrow + r] = vb.y;
            Bs[lk + 2][lrow + r] = vb.z;
            Bs[lk + 3][lrow + r] = vb.w;
        }
        __syncthreads();

        #pragma unroll
        for (int k = 0; k < BK; k++) {
            float4 a0 = *(const float4*)&As[k][tr];
            float4 a1 = *(const float4*)&As[k][tr + 4];
            float4 b0 = *(const float4*)&Bs[k][tc];
            float4 b1 = *(const float4*)&Bs[k][tc + 4];
            float a[TM] = {a0.x, a0.y, a0.z, a0.w, a1.x, a1.y, a1.z, a1.w};
            float b[TN] = {b0.x, b0.y, b0.z, b0.w, b1.x, b1.y, b1.z, b1.w};
            #pragma unroll
            for (int i = 0; i < TM; i++)
                #pragma unroll
                for (int j = 0; j < TN; j++)
                    acc[i][j] = fmaf(a[i], b[j], acc[i][j]);
        }
        __syncthreads();
    }
}

// ---------------------------------------------------------------------------
// Kernel 1: min/max over the full NxN Gram matrix. Only upper-triangular
// tiles (ti <= tj) are computed; symmetry covers the rest. No stores of sims.
// ---------------------------------------------------------------------------
__global__ __launch_bounds__(NTHREADS) void lp_minmax_kernel(const float* __restrict__ E)
{
    const int ti = blockIdx.y;
    const int tj = blockIdx.x;
    if (ti > tj) return;   // lower-tri tile: redundant by symmetry

    float acc[TM][TN];
    #pragma unroll
    for (int i = 0; i < TM; i++)
        #pragma unroll
        for (int j = 0; j < TN; j++)
            acc[i][j] = 0.0f;

    gram_tile_128x128(E + (size_t)ti * BM * DIM,
                      E + (size_t)tj * BN * DIM, acc);

    // Thread-local min/max over the 8x8 tile.
    float lmin = acc[0][0], lmax = acc[0][0];
    #pragma unroll
    for (int i = 0; i < TM; i++)
        #pragma unroll
        for (int j = 0; j < TN; j++) {
            lmin = fminf(lmin, acc[i][j]);
            lmax = fmaxf(lmax, acc[i][j]);
        }

    // Warp reduce.
    #pragma unroll
    for (int off = 16; off > 0; off >>= 1) {
        lmin = fminf(lmin, __shfl_xor_sync(0xffffffffu, lmin, off));
        lmax = fmaxf(lmax, __shfl_xor_sync(0xffffffffu, lmax, off));
    }

    __shared__ float smin[NTHREADS / 32];
    __shared__ float smax[NTHREADS / 32];
    const int wid  = threadIdx.x >> 5;
    const int lane = threadIdx.x & 31;
    if (lane == 0) { smin[wid] = lmin; smax[wid] = lmax; }
    __syncthreads();
    if (threadIdx.x == 0) {
        float m = smin[0], M = smax[0];
        #pragma unroll
        for (int w = 1; w < NTHREADS / 32; w++) {
            m = fminf(m, smin[w]);
            M = fmaxf(M, smax[w]);
        }
        atomicMin(&g_min_key, f2key(m));
        atomicMax(&g_max_key, f2key(M));
    }
}

// ---------------------------------------------------------------------------
// Kernel 2: per-graph 128x128 Gram block, normalize, scatter strict upper
// triangle (row-major np.triu_indices order) to output.
// p(r,c) = r*(G-1) - r*(r-1)/2 + (c - r - 1)
// ---------------------------------------------------------------------------
__global__ __launch_bounds__(NTHREADS) void lp_diag_kernel(
    const float* __restrict__ E, float* __restrict__ out)
{
    const int g = blockIdx.x;
    const float* base = E + (size_t)g * GSZ * DIM;

    float acc[TM][TN];
    #pragma unroll
    for (int i = 0; i < TM; i++)
        #pragma unroll
        for (int j = 0; j < TN; j++)
            acc[i][j] = 0.0f;

    gram_tile_128x128(base, base, acc);

    const float m   = key2f(g_min_key);
    const float M   = key2f(g_max_key);
    const float inv = 1.0f / (M - m + 1e-7f);

    const int tr = (threadIdx.x >> 4) << 3;
    const int tc = (threadIdx.x & 15) << 3;
    float* o = out + (size_t)g * NPAIR;

    #pragma unroll
    for (int i = 0; i < TM; i++) {
        const int r = tr + i;
        // p = rowbase + c  for c > r
        const int rowbase = r * (GSZ - 1) - (r * (r - 1)) / 2 - r - 1;
        #pragma unroll
        for (int j = 0; j < TN; j++) {
            const int c = tc + j;
            if (c > r)
                o[rowbase + c] = (acc[i][j] - m) * inv;
        }
    }
}

// ---------------------------------------------------------------------------
// Launch: init -> triangular minmax GEMM -> diagonal gram + gather.
// All graph-capturable (kernel launches only, no allocs, no syncs).
// ---------------------------------------------------------------------------
extern "C" void kernel_launch(void* const* d_in, const int* in_sizes, int n_in,
                              void* d_out, int out_size)
{
    const float* E = (const float*)d_in[0];
    float* out = (float*)d_out;
    (void)in_sizes; (void)n_in; (void)out_size;

    lp_init_kernel<<<1, 1>>>();

    dim3 grid(NTOT / BN, NTOT / BM);   // 128 x 128 tiles, lower-tri blocks exit early
    lp_minmax_kernel<<<grid, NTHREADS>>>(E);

    lp_diag_kernel<<<NG, NTHREADS>>>(E, out);
}

// round 3
// speedup vs baseline: 7.9654x; 7.9654x over previous
#include <cuda_runtime.h>
#include <cuda_bf16.h>
#include <cstdint>
#include <cstddef>

// ---------------------------------------------------------------------------
// Problem constants
// ---------------------------------------------------------------------------
#define NG    128
#define GSZ   128
#define DIM   512
#define NTOT  (NG * GSZ)               // 16384
#define NPAIR (GSZ * (GSZ - 1) / 2)    // 8128

// GEMM tiling
#define BM 256
#define BN 128
#define BK 64
#define KT (DIM / BK)                  // 8 k-tiles
#define NSTG 3
#define THREADS 512

// smem: A stages 256x64 bf16 = 32KB each; B stages 128x64 bf16 = 16KB each
#define SA_BYTES (BM * BK * 2)
#define SB_BYTES (BN * BK * 2)
#define SOFF_B   (NSTG * SA_BYTES)
#define SMEM_TOTAL (NSTG * (SA_BYTES + SB_BYTES))   // 144 KB

// ---------------------------------------------------------------------------
// Device globals
// ---------------------------------------------------------------------------
__device__ __align__(16) __nv_bfloat16 g_Ebf[(size_t)NTOT * DIM];   // 16 MB
__device__ float g_scratch[(size_t)NG * GSZ * GSZ];                 // 8 MB
__device__ unsigned g_min_key;
__device__ unsigned g_max_key;

__device__ __forceinline__ unsigned f2key(float f) {
    unsigned b = __float_as_uint(f);
    return (b & 0x80000000u) ? ~b : (b | 0x80000000u);
}
__device__ __forceinline__ float key2f(unsigned k) {
    unsigned b = (k & 0x80000000u) ? (k ^ 0x80000000u) : ~k;
    return __uint_as_float(b);
}

// ---------------------------------------------------------------------------
// PTX helpers (baseline sm_80+ only — no arch-suffix features)
// ---------------------------------------------------------------------------
__device__ __forceinline__ uint32_t smem_u32(const void* p) {
    uint32_t a;
    asm("{ .reg .u64 t; cvta.to.shared.u64 t, %1; cvt.u32.u64 %0, t; }" : "=r"(a) : "l"(p));
    return a;
}

#define CP_ASYNC16(s, g) \
    asm volatile("cp.async.cg.shared.global [%0], [%1], 16;" :: "r"(s), "l"(g) : "memory")
#define CP_COMMIT() asm volatile("cp.async.commit_group;" ::: "memory")
#define CP_WAIT2()  asm volatile("cp.async.wait_group 2;" ::: "memory")

#define LDMATRIX_X4(r0, r1, r2, r3, addr) \
    asm volatile("ldmatrix.sync.aligned.m8n8.x4.shared.b16 {%0,%1,%2,%3}, [%4];" \
        : "=r"(r0), "=r"(r1), "=r"(r2), "=r"(r3) : "r"(addr))

#define MMA_16816(c0, c1, c2, c3, a0, a1, a2, a3, b0, b1) \
    asm volatile("mma.sync.aligned.m16n8k16.row.col.f32.bf16.bf16.f32 " \
        "{%0,%1,%2,%3}, {%4,%5,%6,%7}, {%8,%9}, {%0,%1,%2,%3};" \
        : "+f"(c0), "+f"(c1), "+f"(c2), "+f"(c3) \
        : "r"(a0), "r"(a1), "r"(a2), "r"(a3), "r"(b0), "r"(b1))

// swizzle: byte off within a 128B-row tile; xor bits[6:4] with row bits[2:0]
__device__ __forceinline__ uint32_t swz(uint32_t off) {
    return off ^ ((off >> 3) & 0x70);
}

// ---------------------------------------------------------------------------
// init
// ---------------------------------------------------------------------------
__global__ void lp_init_kernel() {
    g_min_key = 0xFFFFFFFFu;
    g_max_key = 0u;
}

// ---------------------------------------------------------------------------
// fp32 -> bf16 row-major convert (8 elems / thread)
// ---------------------------------------------------------------------------
__device__ __forceinline__ uint32_t pack_bf2(float a, float b) {
    uint32_t lo = (uint32_t)__bfloat16_as_ushort(__float2bfloat16_rn(a));
    uint32_t hi = (uint32_t)__bfloat16_as_ushort(__float2bfloat16_rn(b));
    return lo | (hi << 16);
}

__global__ __launch_bounds__(256) void lp_convert_kernel(const float* __restrict__ E) {
    size_t t = (size_t)blockIdx.x * blockDim.x + threadIdx.x;   // 0..1048575
    const float4* src = (const float4*)(E + t * 8);
    float4 f0 = src[0], f1 = src[1];
    uint4 p = make_uint4(pack_bf2(f0.x, f0.y), pack_bf2(f0.z, f0.w),
                         pack_bf2(f1.x, f1.y), pack_bf2(f1.z, f1.w));
    *(uint4*)(g_Ebf + t * 8) = p;
}

// ---------------------------------------------------------------------------
// Main GEMM: grid (128, 64). CTA = 256x128 output tile at rows ti*256,
// cols tj*128. Keep only tj >= 2*ti (upper coverage incl. diagonal).
// 512 threads = 16 warps, warp tile 32x64 (grid 8m x 2n).
// ---------------------------------------------------------------------------
__global__ __launch_bounds__(THREADS, 1) void lp_mm_kernel() {
    const int tj = blockIdx.x;
    const int ti = blockIdx.y;
    if (tj < 2 * ti) return;

    extern __shared__ __align__(128) unsigned char smem[];
    const uint32_t sb = smem_u32(smem);

    const int tid  = threadIdx.x;
    const int wid  = tid >> 5;
    const int lane = tid & 31;
    const int wm   = (wid >> 1) * 32;    // 0..224
    const int wn   = (wid & 1) * 64;     // 0 or 64

    const __nv_bfloat16* __restrict__ Abase = g_Ebf + (size_t)ti * BM * DIM;
    const __nv_bfloat16* __restrict__ Bbase = g_Ebf + (size_t)tj * BN * DIM;

    // tile loaders: 16B per cp.async; A: 2048 chunks (4/thread), B: 1024 (2/thread)
    auto loadA = [&](int stage, int kt) {
        const uint32_t sbase = sb + stage * SA_BYTES;
        const __nv_bfloat16* src = Abase + kt * BK;
        #pragma unroll
        for (int i = 0; i < 4; i++) {
            int id  = tid + i * THREADS;
            int row = id >> 3, c8 = id & 7;
            CP_ASYNC16(sbase + swz((uint32_t)(row * 128 + c8 * 16)),
                       src + (size_t)row * DIM + c8 * 8);
        }
    };
    auto loadB = [&](int stage, int kt) {
        const uint32_t sbase = sb + SOFF_B + stage * SB_BYTES;
        const __nv_bfloat16* src = Bbase + kt * BK;
        #pragma unroll
        for (int i = 0; i < 2; i++) {
            int id  = tid + i * THREADS;
            int row = id >> 3, c8 = id & 7;
            CP_ASYNC16(sbase + swz((uint32_t)(row * 128 + c8 * 16)),
                       src + (size_t)row * DIM + c8 * 8);
        }
    };

    float acc[2][8][4];
    #pragma unroll
    for (int mt = 0; mt < 2; mt++)
        #pragma unroll
        for (int n8 = 0; n8 < 8; n8++)
            #pragma unroll
            for (int r = 0; r < 4; r++)
                acc[mt][n8][r] = 0.0f;

    // prologue: stages 0,1
    loadA(0, 0); loadB(0, 0); CP_COMMIT();
    loadA(1, 1); loadB(1, 1); CP_COMMIT();

    // precomputed per-thread fragment rows
    const int arow_lo = (lane & 15);        // within m16 tile
    const int akb     = ((lane >> 4) << 4); // 0 or 16 bytes
    const int brow_in = ((lane >> 4) << 3) + (lane & 7); // 0..15
    const int bkb     = ((lane >> 3) & 1) << 4;          // 0 or 16 bytes

    for (int kt = 0; kt < KT; kt++) {
        if (kt + 2 < KT) {
            int s2 = (kt + 2) % NSTG;
            loadA(s2, kt + 2);
            loadB(s2, kt + 2);
        }
        CP_COMMIT();
        CP_WAIT2();
        __syncthreads();

        const int st = kt % NSTG;
        const uint32_t sA = sb + st * SA_BYTES;
        const uint32_t sB = sb + SOFF_B + st * SB_BYTES;

        #pragma unroll
        for (int kk = 0; kk < 4; kk++) {
            uint32_t a[2][4];
            #pragma unroll
            for (int mt = 0; mt < 2; mt++) {
                int row = wm + mt * 16 + arow_lo;
                uint32_t kb = (uint32_t)(kk * 32 + akb);
                uint32_t addr = sA + row * 128 + (kb ^ ((row & 7) << 4));
                LDMATRIX_X4(a[mt][0], a[mt][1], a[mt][2], a[mt][3], addr);
            }
            uint32_t b[4][4];
            #pragma unroll
            for (int nb = 0; nb < 4; nb++) {
                int row = wn + nb * 16 + brow_in;
                uint32_t kb = (uint32_t)(kk * 32 + bkb);
                uint32_t addr = sB + row * 128 + (kb ^ ((row & 7) << 4));
                LDMATRIX_X4(b[nb][0], b[nb][1], b[nb][2], b[nb][3], addr);
            }
            #pragma unroll
            for (int mt = 0; mt < 2; mt++)
                #pragma unroll
                for (int nb = 0; nb < 4; nb++) {
                    MMA_16816(acc[mt][2*nb][0], acc[mt][2*nb][1], acc[mt][2*nb][2], acc[mt][2*nb][3],
                              a[mt][0], a[mt][1], a[mt][2], a[mt][3],
                              b[nb][0], b[nb][1]);
                    MMA_16816(acc[mt][2*nb+1][0], acc[mt][2*nb+1][1], acc[mt][2*nb+1][2], acc[mt][2*nb+1][3],
                              a[mt][0], a[mt][1], a[mt][2], a[mt][3],
                              b[nb][2], b[nb][3]);
                }
        }
        __syncthreads();
    }

    // ------------------- epilogue -------------------
    float lmin = 3.4e38f, lmax = -3.4e38f;
    #pragma unroll
    for (int mt = 0; mt < 2; mt++)
        #pragma unroll
        for (int n8 = 0; n8 < 8; n8++)
            #pragma unroll
            for (int r = 0; r < 4; r++) {
                float v = acc[mt][n8][r];
                lmin = fminf(lmin, v);
                lmax = fmaxf(lmax, v);
            }

    // diagonal 128x128 block spill (raw, pre-normalization)
    if ((tj >> 1) == ti) {
        const int mbase = ti * BM + wm;
        const int nbase = tj * BN + wn;
        #pragma unroll
        for (int mt = 0; mt < 2; mt++)
            #pragma unroll
            for (int n8 = 0; n8 < 8; n8++)
                #pragma unroll
                for (int r = 0; r < 4; r++) {
                    int mg = mbase + mt * 16 + (lane >> 2) + ((r >> 1) << 3);
                    int ng = nbase + n8 * 8 + ((lane & 3) << 1) + (r & 1);
                    if ((mg >> 7) == (ng >> 7)) {
                        int g = mg >> 7;
                        g_scratch[((size_t)g * GSZ + (mg & 127)) * GSZ + (ng & 127)] =
                            acc[mt][n8][r];
                    }
                }
    }

    // warp reduce + one atomic pair per warp
    #pragma unroll
    for (int off = 16; off > 0; off >>= 1) {
        lmin = fminf(lmin, __shfl_xor_sync(0xffffffffu, lmin, off));
        lmax = fmaxf(lmax, __shfl_xor_sync(0xffffffffu, lmax, off));
    }
    if (lane == 0) {
        atomicMin(&g_min_key, f2key(lmin));
        atomicMax(&g_max_key, f2key(lmax));
    }
}

// ---------------------------------------------------------------------------
// normalize diag scratch -> output (np.triu_indices row-major order)
// ---------------------------------------------------------------------------
__global__ __launch_bounds__(256) void lp_norm_kernel(float* __restrict__ out) {
    const int g = blockIdx.x;
    const float m = key2f(g_min_key);
    const float M = key2f(g_max_key);
    const float inv = 1.0f / (M - m + 1e-7f);
    const float* s = g_scratch + (size_t)g * GSZ * GSZ;
    float* o = out + (size_t)g * NPAIR;
    for (int idx = threadIdx.x; idx < GSZ * GSZ; idx += blockDim.x) {
        const int r = idx >> 7, c = idx & 127;
        if (c > r) {
            const int p = r * (GSZ - 1) - (r * (r - 1)) / 2 + (c - r - 1);
            o[p] = (s[idx] - m) * inv;
        }
    }
}

// ---------------------------------------------------------------------------
// kernel_launch
// ---------------------------------------------------------------------------
extern "C" void kernel_launch(void* const* d_in, const int* in_sizes, int n_in,
                              void* d_out, int out_size)
{
    const float* E = (const float*)d_in[0];
    float* out = (float*)d_out;
    (void)in_sizes; (void)n_in; (void)out_size;

    static bool attr_set = false;
    if (!attr_set) {
        cudaFuncSetAttribute(lp_mm_kernel,
                             cudaFuncAttributeMaxDynamicSharedMemorySize, SMEM_TOTAL);
        attr_set = true;
    }

    lp_convert_kernel<<<4096, 256>>>(E);
    lp_init_kernel<<<1, 1>>>();
    lp_mm_kernel<<<dim3(128, 64), THREADS, SMEM_TOTAL>>>();
    lp_norm_kernel<<<NG, 256>>>(out);
}